// round 6
// baseline (speedup 1.0000x reference)
#include <cuda_runtime.h>
#include <cuda_bf16.h>
#include <cstdint>
#include <cstddef>

// ---------------------------------------------------------------------------
// FeatureMatching — R5: wave-quantization / occupancy round.
//  * conv2 moved to TH=8 tiles + occ 3 (util 61% -> 81%)
//  * match GEMM split-K=3 + occ 3 (432 blocks ~= one full occ-3 wave)
//  * everything else as R4 (merged q+k launches, f32x2 packed math)
// ---------------------------------------------------------------------------

#define B_ 2

// buffer part offsets (floats)
#define KOFF12 (2*64*192*192)     // k-part offset in BUF1/BUF2
#define KOFF3  (2*64*96*96)       // k-part offset in BUF3
#define KOFF4  (2*128*96*96)      // k-part offset in BUF4

// ---- scratch (device globals; allocation is forbidden) ----
static __device__ float g_buf1[2*64*(192*192 + 96*96)];
static __device__ float g_buf2[2*64*(192*192 + 96*96)];
static __device__ float g_buf3[2*64*(96*96 + 48*48)];
static __device__ float g_buf4[2*128*(96*96 + 48*48)];
static __device__ float g_kin [2*3*96*96];
static __device__ float g_qf  [2*16*96*96];
static __device__ float g_kf  [2*16*48*48];
static __device__ float g_Sq  [2*96*96];
static __device__ float g_Nq  [2*96*96];
static __device__ float g_Sk  [2*48*48];
static __device__ float g_Nk  [2*48*48];
static __device__ float g_Qn  [2*144*9216];
static __device__ float g_Wn  [2*2304*144];
static __device__ float g_pV  [2*3*9216];
static __device__ int   g_pI  [2*3*9216];

#define BUF1 1
#define BUF2 2
#define BUF3 3
#define BUF4 4
#define KIN  5

__device__ __forceinline__ float* bufsel(int id) {
    switch (id) {
        case BUF1: return g_buf1;
        case BUF2: return g_buf2;
        case BUF3: return g_buf3;
        case BUF4: return g_buf4;
        case KIN:  return g_kin;
    }
    return nullptr;
}

__device__ __forceinline__ int reflect_idx(int i, int n) {
    if (i < 0) return -i;
    if (i >= n) return 2*n - 2 - i;
    return i;
}

// ---- packed f32x2 helpers (Blackwell sm_100+) ----
__device__ __forceinline__ unsigned long long pack2(float lo, float hi) {
    unsigned long long r;
    asm("mov.b64 %0, {%1, %2};" : "=l"(r) : "f"(lo), "f"(hi));
    return r;
}
__device__ __forceinline__ float2 unpack2(unsigned long long v) {
    float2 f;
    asm("mov.b64 {%0, %1}, %2;" : "=f"(f.x), "=f"(f.y) : "l"(v));
    return f;
}
__device__ __forceinline__ void ffma2(unsigned long long& d,
                                      unsigned long long a, unsigned long long b) {
    asm("fma.rn.f32x2 %0, %1, %2, %3;" : "=l"(d) : "l"(a), "l"(b), "l"(d));
}

// ---------------------------------------------------------------------------
// avg-pool 2x2 stride 2 (key [2,3,192,192] -> KIN [2,3,96,96])
// ---------------------------------------------------------------------------
__global__ void avgpool2_kernel(const float* __restrict__ x) {
    float* y = g_kin;
    const int H = 192, W = 192, Ho = 96, Wo = 96;
    int n = 2*3*Ho*Wo;
    int i = blockIdx.x * 256 + threadIdx.x;
    if (i >= n) return;
    int wo = i % Wo; int t = i / Wo; int ho = t % Ho; int c = t / Ho;
    const float* p = x + ((size_t)c * H + (size_t)ho * 2) * W + (size_t)wo * 2;
    y[i] = 0.25f * (p[0] + p[1] + p[W] + p[W + 1]);
}

// ---------------------------------------------------------------------------
// merged max-pool 2x2: q part (64ch @192->96) + k part (64ch @96->48)
// ---------------------------------------------------------------------------
__global__ void maxpool2_m_kernel() {
    const int nq = 2*64*96*96;
    const int nk = 2*64*48*48;
    int i = blockIdx.x * 256 + threadIdx.x;
    const float* x; float* y; int H, W, idx;
    if (i < nq) { x = g_buf2; y = g_buf3; H = 192; W = 192; idx = i; }
    else {
        idx = i - nq;
        if (idx >= nk) return;
        x = g_buf2 + KOFF12; y = g_buf3 + KOFF3; H = 96; W = 96;
    }
    int Ho = H >> 1, Wo = W >> 1;
    int wo = idx % Wo; int t = idx / Wo; int ho = t % Ho; int c = t / Ho;
    const float* p = x + ((size_t)c * H + (size_t)ho * 2) * W + (size_t)wo * 2;
    y[idx] = fmaxf(fmaxf(p[0], p[1]), fmaxf(p[W], p[W + 1]));
}

// ---------------------------------------------------------------------------
// merged 3x3 conv (zero pad 1) + ReLU, packed f32x2, two jobs per launch
// (query-path resolution + key-path resolution; same weights).
// TH=16: 16x16 tile, lane = 8-px run, occ 2.  TH=8: 16x8 tile, 4-px run, occ 3.
// warp -> 8-oc group (weight LDS warp-uniform broadcast).
// grid: (nt0 + nt1, 1, B * OC/64)
// ---------------------------------------------------------------------------
template<int CHUNK, int TH>
__global__ __launch_bounds__(256, (TH == 8) ? 3 : 2)
void conv3x3_m_kernel(const float* x0ext, int x0id, long x0off, int y0id, long y0off,
                      int H0, int W0, int ntx0, int nt0,
                      int x1id, long x1off, int y1id, long y1off,
                      int H1, int W1, int ntx1,
                      const float* __restrict__ w, const float* __restrict__ bias,
                      int IC, int OC) {
    constexpr int PX = (TH == 8) ? 4 : 8;
    constexpr int TW = 16;
    __shared__ float sIn[CHUNK][TH + 2][TW + 4];
    __shared__ float sW[CHUNK][9][64];

    int t = blockIdx.x;
    const float* x; float* y; int H, W, tx, ty;
    if (t < nt0) {
        x = x0ext ? x0ext : bufsel(x0id) + x0off;
        y = bufsel(y0id) + y0off;
        H = H0; W = W0; tx = t % ntx0; ty = t / ntx0;
    } else {
        t -= nt0;
        x = bufsel(x1id) + x1off;
        y = bufsel(y1id) + y1off;
        H = H1; W = W1; tx = t % ntx1; ty = t / ntx1;
    }

    const int ocg = OC >> 6;
    const int b = blockIdx.z / ocg;
    const int ocbase = (blockIdx.z % ocg) << 6;
    const int tid = threadIdx.x;
    const int wid = tid >> 5, lane = tid & 31;
    const int r  = (TH == 8) ? (lane >> 2) : (lane >> 1);
    const int xo = (TH == 8) ? ((lane & 3) << 2) : ((lane & 1) << 3);
    const int x0p = tx * TW, y0p = ty * TH;
    const int HW = H * W;
    const float* xb = x + (size_t)b * IC * HW;

    unsigned long long acc[4][PX];
#pragma unroll
    for (int p = 0; p < 4; p++)
#pragma unroll
        for (int j = 0; j < PX; j++) acc[p][j] = 0ULL;

    for (int ic0 = 0; ic0 < IC; ic0 += CHUNK) {
        __syncthreads();
        const int TOT = CHUNK * (TH + 2) * (TW + 2);
        for (int i = tid; i < TOT; i += 256) {
            int ic = i / ((TH + 2) * (TW + 2)); int rr = i % ((TH + 2) * (TW + 2));
            int iy = rr / (TW + 2), ix = rr % (TW + 2);
            int gy = y0p + iy - 1, gx = x0p + ix - 1;
            float v = 0.f;
            if (gy >= 0 && gy < H && gx >= 0 && gx < W)
                v = xb[(size_t)(ic0 + ic) * HW + (size_t)gy * W + gx];
            sIn[ic][iy][ix] = v;
        }
        for (int i = tid; i < CHUNK * 9 * 64; i += 256) {
            int oc = i & 63; int rr = i >> 6; int k = rr % 9; int ic = rr / 9;
            sW[ic][k][oc] = w[((size_t)(ocbase + oc) * IC + (ic0 + ic)) * 9 + k];
        }
        __syncthreads();

#pragma unroll
        for (int ic = 0; ic < CHUNK; ic++) {
#pragma unroll
            for (int ky = 0; ky < 3; ky++) {
                unsigned long long vv[PX + 2];
#pragma unroll
                for (int u = 0; u < PX + 2; u++) {
                    float v = sIn[ic][r + ky][xo + u];
                    vv[u] = pack2(v, v);
                }
#pragma unroll
                for (int kx = 0; kx < 3; kx++) {
                    const ulonglong2* wp = (const ulonglong2*)&sW[ic][ky * 3 + kx][wid * 8];
                    ulonglong2 wA = wp[0];
                    ulonglong2 wB = wp[1];
#pragma unroll
                    for (int j = 0; j < PX; j++) {
                        ffma2(acc[0][j], wA.x, vv[kx + j]);
                        ffma2(acc[1][j], wA.y, vv[kx + j]);
                        ffma2(acc[2][j], wB.x, vv[kx + j]);
                        ffma2(acc[3][j], wB.y, vv[kx + j]);
                    }
                }
            }
        }
    }

    const int ocw = ocbase + wid * 8;
    const int oy = y0p + r, ox = x0p + xo;
#pragma unroll
    for (int p = 0; p < 4; p++) {
        float blo = bias[ocw + 2*p], bhi = bias[ocw + 2*p + 1];
        float lo[PX], hi[PX];
#pragma unroll
        for (int j = 0; j < PX; j++) {
            float2 u = unpack2(acc[p][j]);
            lo[j] = fmaxf(u.x + blo, 0.f);
            hi[j] = fmaxf(u.y + bhi, 0.f);
        }
        float* ylo = y + ((size_t)b * OC + ocw + 2*p) * HW + (size_t)oy * W + ox;
        float* yhi = ylo + HW;
#pragma unroll
        for (int q4 = 0; q4 < PX / 4; q4++) {
            *(float4*)(ylo + q4 * 4) = make_float4(lo[q4*4], lo[q4*4+1], lo[q4*4+2], lo[q4*4+3]);
            *(float4*)(yhi + q4 * 4) = make_float4(hi[q4*4], hi[q4*4+1], hi[q4*4+2], hi[q4*4+3]);
        }
    }
}

// ---------------------------------------------------------------------------
// merged 1x1 conv 128->16 + LeakyReLU(0.2) + fused channel-ssq.
// grid: (36 + 9, B).  bx<36 -> q job, else k job.
// ---------------------------------------------------------------------------
__global__ void conv1x1_leaky_ssq_kernel(const float* __restrict__ w,
                                         const float* __restrict__ bias) {
    __shared__ float sw[128 * 16];   // [ic][oc]
    const int tid = threadIdx.x;
    for (int i = tid; i < 2048; i += 256) {
        int oc = i & 15, ic = i >> 4;
        sw[i] = w[oc * 128 + ic];
    }
    __syncthreads();
    const int bx = blockIdx.x;
    const int b = blockIdx.y;
    const float* x; float* y; float* S; int HW, pix;
    if (bx < 36) { x = g_buf4;         y = g_qf; S = g_Sq; HW = 9216; pix = bx * 256 + tid; }
    else         { x = g_buf4 + KOFF4; y = g_kf; S = g_Sk; HW = 2304; pix = (bx - 36) * 256 + tid; }

    const float* xb = x + (size_t)b * 128 * HW + pix;
    float acc[16];
#pragma unroll
    for (int o = 0; o < 16; o++) acc[o] = bias[o];
    for (int ic = 0; ic < 128; ic++) {
        const float v = xb[(size_t)ic * HW];
        const float4* wp = (const float4*)&sw[ic * 16];
#pragma unroll
        for (int o4 = 0; o4 < 4; o4++) {
            float4 w4 = wp[o4];
            acc[o4*4+0] += v * w4.x;
            acc[o4*4+1] += v * w4.y;
            acc[o4*4+2] += v * w4.z;
            acc[o4*4+3] += v * w4.w;
        }
    }
    float* yb = y + (size_t)b * 16 * HW + pix;
    float ssq = 0.f;
#pragma unroll
    for (int o = 0; o < 16; o++) {
        float v = acc[o];
        v = v > 0.f ? v : 0.2f * v;
        yb[(size_t)o * HW] = v;
        ssq += v * v;
    }
    S[(size_t)b * HW + pix] = ssq;
}

// ---------------------------------------------------------------------------
// merged patch inv-norm: 3x3 reflected neighbor sum -> 1/max(sqrt, 1e-12)
// ---------------------------------------------------------------------------
__global__ void patch_invnorm_m_kernel() {
    const int nq = 2*9216;
    int i = blockIdx.x * 256 + threadIdx.x;
    const float* S; float* N; int H, W, idx;
    if (i < nq) { S = g_Sq; N = g_Nq; H = 96; W = 96; idx = i; }
    else {
        idx = i - nq;
        if (idx >= 2*2304) return;
        S = g_Sk; N = g_Nk; H = 48; W = 48;
    }
    int HW = H * W;
    int pix = idx % HW; int b = idx / HW;
    int y = pix / W, x = pix % W;
    float s = 0.f;
#pragma unroll
    for (int dy = -1; dy <= 1; dy++) {
        int ry = reflect_idx(y + dy, H);
#pragma unroll
        for (int dx = -1; dx <= 1; dx++) {
            int rx = reflect_idx(x + dx, W);
            s += S[(size_t)b * HW + (size_t)ry * W + rx];
        }
    }
    N[idx] = 1.f / fmaxf(sqrtf(s), 1e-12f);
}

// ---------------------------------------------------------------------------
// Build Qn [B][144][9216]
// ---------------------------------------------------------------------------
__global__ void build_qn_kernel() {
    const float* qf = g_qf;
    const float* Nq = g_Nq;
    float* Qn = g_Qn;
    const int W = 96, HW = 9216;
    int pix = blockIdx.x * 256 + threadIdx.x;
    int bf = blockIdx.y;
    int b = bf / 144, f = bf % 144;
    int c = f / 9, k = f % 9;
    int dy = k / 3 - 1, dx = k % 3 - 1;
    int y = pix / W, x = pix % W;
    int ry = reflect_idx(y + dy, 96), rx = reflect_idx(x + dx, 96);
    Qn[((size_t)b * 144 + f) * HW + pix] =
        qf[((size_t)b * 16 + c) * HW + (size_t)ry * W + rx] * Nq[(size_t)b * HW + pix];
}

// ---------------------------------------------------------------------------
// Build Wn [B][2304][144]
// ---------------------------------------------------------------------------
__global__ void build_wn_kernel() {
    const float* kf = g_kf;
    const float* Nk = g_Nk;
    float* Wn = g_Wn;
    const int W = 48, HW = 2304;
    int idx = blockIdx.x * 256 + threadIdx.x;
    if (idx >= B_ * HW * 144) return;
    int f = idx % 144; int r = idx / 144;
    int kp = r % HW; int b = r / HW;
    int c = f / 9, k = f % 9;
    int dy = k / 3 - 1, dx = k % 3 - 1;
    int y = kp / W, x = kp % W;
    int ry = reflect_idx(y + dy, 48), rx = reflect_idx(x + dx, 48);
    Wn[((size_t)b * HW + kp) * 144 + f] =
        kf[((size_t)b * 16 + c) * HW + (size_t)ry * W + rx] * Nk[(size_t)b * HW + kp];
}

// ---------------------------------------------------------------------------
// Fused cosine-GEMM + max/argmax, packed f32x2, split-K over 3 thirds, occ 3.
// Block tile = 64 keys x 128 queries; each block covers 768 keys (one third).
// warp -> 8-key group (ulonglong2 broadcast), lane -> 4-query group.
// grid: (72, B, 3) = 432 blocks ~ one full occ-3 wave (444 slots)
// ---------------------------------------------------------------------------
__global__ __launch_bounds__(256, 3)
void match_f32x2_kernel() {
    const int LQ = 9216, LK = 2304, F = 144;
    __shared__ float sA[48][64];    // [f][k]
    __shared__ float sB[48][128];   // [f][q]
    __shared__ float rV[8][128];
    __shared__ int   rI[8][128];

    const int tid = threadIdx.x;
    const int wid = tid >> 5, lane = tid & 31;
    const int q0 = blockIdx.x << 7;
    const int b = blockIdx.y;
    const int z = blockIdx.z;
    const float* Wb = g_Wn + (size_t)b * LK * F;
    const float* Qb = g_Qn + (size_t)b * F * LQ;

    const int lk = tid & 63;
    const int cb = (tid >> 6) * 3;
    const int fB = tid >> 5;
    const int cB = tid & 31;

    float bestV[4] = {-1e30f, -1e30f, -1e30f, -1e30f};
    int   bestI[4] = {0, 0, 0, 0};

    const int kbeg = z * 768, kend = kbeg + 768;
    for (int k0 = kbeg; k0 < kend; k0 += 64) {
        unsigned long long acc[4][4];
#pragma unroll
        for (int p = 0; p < 4; p++)
#pragma unroll
            for (int j = 0; j < 4; j++) acc[p][j] = 0ULL;

        for (int f0 = 0; f0 < F; f0 += 48) {
            __syncthreads();
#pragma unroll
            for (int e = 0; e < 3; e++) {
                int c = cb + e;
                float4 a4 = *(const float4*)&Wb[(size_t)(k0 + lk) * F + f0 + c * 4];
                sA[c*4+0][lk] = a4.x; sA[c*4+1][lk] = a4.y;
                sA[c*4+2][lk] = a4.z; sA[c*4+3][lk] = a4.w;
            }
#pragma unroll
            for (int p = 0; p < 6; p++) {
                int f = fB + (p << 3);
                *(float4*)&sB[f][cB * 4] =
                    *(const float4*)&Qb[(size_t)(f0 + f) * LQ + q0 + cB * 4];
            }
            __syncthreads();

#pragma unroll 6
            for (int f = 0; f < 48; f++) {
                ulonglong2 a01 = *(const ulonglong2*)&sA[f][wid * 8];
                ulonglong2 a23 = *(const ulonglong2*)&sA[f][wid * 8 + 4];
                float4 b4 = *(const float4*)&sB[f][lane * 4];
                unsigned long long b0 = pack2(b4.x, b4.x);
                unsigned long long b1 = pack2(b4.y, b4.y);
                unsigned long long b2 = pack2(b4.z, b4.z);
                unsigned long long b3 = pack2(b4.w, b4.w);
                ffma2(acc[0][0], a01.x, b0); ffma2(acc[0][1], a01.x, b1);
                ffma2(acc[0][2], a01.x, b2); ffma2(acc[0][3], a01.x, b3);
                ffma2(acc[1][0], a01.y, b0); ffma2(acc[1][1], a01.y, b1);
                ffma2(acc[1][2], a01.y, b2); ffma2(acc[1][3], a01.y, b3);
                ffma2(acc[2][0], a23.x, b0); ffma2(acc[2][1], a23.x, b1);
                ffma2(acc[2][2], a23.x, b2); ffma2(acc[2][3], a23.x, b3);
                ffma2(acc[3][0], a23.y, b0); ffma2(acc[3][1], a23.y, b1);
                ffma2(acc[3][2], a23.y, b2); ffma2(acc[3][3], a23.y, b3);
            }
        }

        const int kbase = k0 + wid * 8;
#pragma unroll
        for (int p = 0; p < 4; p++) {
#pragma unroll
            for (int j = 0; j < 4; j++) {
                float2 u = unpack2(acc[p][j]);
                if (u.x > bestV[j]) { bestV[j] = u.x; bestI[j] = kbase + 2*p; }
                if (u.y > bestV[j]) { bestV[j] = u.y; bestI[j] = kbase + 2*p + 1; }
            }
        }
    }

#pragma unroll
    for (int j = 0; j < 4; j++) {
        rV[wid][lane * 4 + j] = bestV[j];
        rI[wid][lane * 4 + j] = bestI[j];
    }
    __syncthreads();
    if (tid < 128) {
        float bv = rV[0][tid]; int bi = rI[0][tid];
#pragma unroll
        for (int t = 1; t < 8; t++) {
            float v = rV[t][tid];
            if (v > bv) { bv = v; bi = rI[t][tid]; }
        }
        int o = (b * 3 + z) * LQ + q0 + tid;
        g_pV[o] = bv;
        g_pI[o] = bi;
    }
}

// ---------------------------------------------------------------------------
// merge the three split-K thirds (z ascending = key ascending; strict >
// keeps the lowest key index on ties, matching jnp.argmax)
// ---------------------------------------------------------------------------
__global__ void match_reduce_kernel(float* __restrict__ relout,
                                    float* __restrict__ idxout) {
    int i = blockIdx.x * 256 + threadIdx.x;
    if (i >= 2 * 9216) return;
    int b = i / 9216, q = i % 9216;
    float bv = g_pV[(b*3+0)*9216 + q]; int bi = g_pI[(b*3+0)*9216 + q];
#pragma unroll
    for (int z = 1; z < 3; z++) {
        float v = g_pV[(b*3+z)*9216 + q];
        if (v > bv) { bv = v; bi = g_pI[(b*3+z)*9216 + q]; }
    }
    relout[i] = bv;
    idxout[i] = (float)bi;
}

// ---------------------------------------------------------------------------
// launcher — ONLY kernel launches
// ---------------------------------------------------------------------------
extern "C" void kernel_launch(void* const* d_in, const int* in_sizes, int n_in,
                              void* d_out, int out_size) {
    const float* query = (const float*)d_in[0];
    const float* key   = (const float*)d_in[1];
    const float* w1 = (const float*)d_in[2];
    const float* b1 = (const float*)d_in[3];
    const float* w2 = (const float*)d_in[4];
    const float* b2 = (const float*)d_in[5];
    const float* w3 = (const float*)d_in[6];
    const float* b3 = (const float*)d_in[7];
    const float* wm = (const float*)d_in[8];
    const float* bm = (const float*)d_in[9];
    float* out = (float*)d_out;

    // key downsample first (conv1 needs it)
    avgpool2_kernel<<<(2*3*96*96 + 255)/256, 256>>>(key);

    // conv1: q@192 (16x16 tiles: 144) + k@96 (36), z = 2  (cheap, IC=3)
    conv3x3_m_kernel<3, 16><<<dim3(180, 1, 2), 256>>>(
        query, 0, 0, BUF1, 0, 192, 192, 12, 144,
        KIN, 0, BUF1, KOFF12, 96, 96, 6,
        w1, b1, 3, 64);

    // conv2: q@192 (16x8 tiles: 12x24=288) + k@96 (6x12=72), z = 2, occ 3
    conv3x3_m_kernel<8, 8><<<dim3(360, 1, 2), 256>>>(
        nullptr, BUF1, 0, BUF2, 0, 192, 192, 12, 288,
        BUF1, KOFF12, BUF2, KOFF12, 96, 96, 6,
        w2, b2, 64, 64);

    // merged maxpool: q 192->96, k 96->48
    maxpool2_m_kernel<<<(2*64*(96*96 + 48*48) + 255)/256, 256>>>();

    // conv3: q@96 (16x8 tiles: 6x12=72) + k@48 (3x6=18), z = 4, occ 3
    conv3x3_m_kernel<8, 8><<<dim3(90, 1, 4), 256>>>(
        nullptr, BUF3, 0, BUF4, 0, 96, 96, 6, 72,
        BUF3, KOFF3, BUF4, KOFF4, 48, 48, 3,
        w3, b3, 64, 128);

    // merged 1x1 + leaky + ssq
    conv1x1_leaky_ssq_kernel<<<dim3(45, 2), 256>>>(wm, bm);

    // merged patch inv-norms
    patch_invnorm_m_kernel<<<(2*(9216 + 2304) + 255)/256, 256>>>();

    // normalized unfold tensors
    build_qn_kernel<<<dim3(36, 2*144), 256>>>();
    build_wn_kernel<<<(2*2304*144 + 255)/256, 256>>>();

    // fused cosine-sim GEMM + max/argmax, split-K=3 then merge
    match_f32x2_kernel<<<dim3(72, 2, 3), 256>>>();
    match_reduce_kernel<<<(2*9216 + 255)/256, 256>>>(out, out + 2*9216);
}

// round 7
// speedup vs baseline: 1.0925x; 1.0925x over previous
#include <cuda_runtime.h>
#include <cuda_bf16.h>
#include <cstdint>
#include <cstddef>

// ---------------------------------------------------------------------------
// FeatureMatching — R6.
//  * conv2 IC-split (720 blocks, wave util 61%->81%); raw partials A/B
//  * maxpool fused into conv3 loader: relu(max2x2(A+B))  (exact reorder)
//  * avgpool fused into conv1 key-job loader
//  * match GEMM restored to proven R4 split-K=2 / occ-2 config
//  * f32x2 packed math everywhere (rt=3 banking floor acknowledged)
// ---------------------------------------------------------------------------

#define B_ 2

#define KOFF12 (2*64*192*192)               // k-region offset in BUF1 / partials
#define KOFF4  (2*128*96*96)                // k-region offset in BUF4
#define PHALF  (2*64*(192*192 + 96*96))     // one conv2 partial (A or B)

// ---- scratch (device globals; allocation is forbidden) ----
static __device__ float g_buf1[2*64*(192*192 + 96*96)];
static __device__ float g_buf2[2ll * PHALF];          // conv2 partials A,B
static __device__ float g_buf4[2*128*(96*96 + 48*48)];
static __device__ float g_qf  [2*16*96*96];
static __device__ float g_kf  [2*16*48*48];
static __device__ float g_Sq  [2*96*96];
static __device__ float g_Nq  [2*96*96];
static __device__ float g_Sk  [2*48*48];
static __device__ float g_Nk  [2*48*48];
static __device__ float g_Qn  [2*144*9216];
static __device__ float g_Wn  [2*2304*144];
static __device__ float g_pV  [2*2*9216];
static __device__ int   g_pI  [2*2*9216];

__device__ __forceinline__ int reflect_idx(int i, int n) {
    if (i < 0) return -i;
    if (i >= n) return 2*n - 2 - i;
    return i;
}

// ---- packed f32x2 helpers (Blackwell sm_100+) ----
__device__ __forceinline__ unsigned long long pack2(float lo, float hi) {
    unsigned long long r;
    asm("mov.b64 %0, {%1, %2};" : "=l"(r) : "f"(lo), "f"(hi));
    return r;
}
__device__ __forceinline__ float2 unpack2(unsigned long long v) {
    float2 f;
    asm("mov.b64 {%0, %1}, %2;" : "=f"(f.x), "=f"(f.y) : "l"(v));
    return f;
}
__device__ __forceinline__ void ffma2(unsigned long long& d,
                                      unsigned long long a, unsigned long long b) {
    asm("fma.rn.f32x2 %0, %1, %2, %3;" : "=l"(d) : "l"(a), "l"(b), "l"(d));
}

// ---------------------------------------------------------------------------
// conv1: 3->64, 3x3 zero-pad, ReLU.  TH=16 tile, CHUNK=IC=3.
// q job: input query @192.  k job: input = avgpool2(key) computed in loader.
// grid: (144 + 36, 1, B)
// ---------------------------------------------------------------------------
__global__ __launch_bounds__(256, 2)
void conv1_kernel(const float* __restrict__ query, const float* __restrict__ key,
                  const float* __restrict__ w, const float* __restrict__ bias) {
    __shared__ float sIn[3][18][20];
    __shared__ float sW[3][9][64];

    int t = blockIdx.x;
    const int b = blockIdx.z;
    const bool qjob = t < 144;
    int H, ntx; const float* src; float* y;
    if (qjob) { H = 192; ntx = 12; src = query + (size_t)b*3*36864; y = g_buf1 + (size_t)b*64*36864; }
    else { t -= 144; H = 96; ntx = 6; src = key + (size_t)b*3*36864; y = g_buf1 + KOFF12 + (size_t)b*64*9216; }
    const int W = H, HW = H * W;
    const int tx = t % ntx, ty = t / ntx;
    const int tid = threadIdx.x;
    const int wid = tid >> 5, lane = tid & 31;
    const int r = lane >> 1, xo = (lane & 1) << 3;
    const int x0p = tx << 4, y0p = ty << 4;

    // load input tile (q: direct; k: 2x2 avg of key@192)
    for (int i = tid; i < 3 * 324; i += 256) {
        int ic = i / 324; int rr = i % 324;
        int iy = rr / 18, ix = rr % 18;
        int gy = y0p + iy - 1, gx = x0p + ix - 1;
        float v = 0.f;
        if (gy >= 0 && gy < H && gx >= 0 && gx < W) {
            if (qjob) {
                v = src[(size_t)ic * 36864 + (size_t)gy * 192 + gx];
            } else {
                const float* p = src + (size_t)ic * 36864 + (size_t)(2*gy) * 192 + 2*gx;
                v = 0.25f * (p[0] + p[1] + p[192] + p[193]);
            }
        }
        sIn[ic][iy][ix] = v;
    }
    for (int i = tid; i < 3 * 9 * 64; i += 256) {
        int oc = i & 63; int rr = i >> 6; int k = rr % 9; int ic = rr / 9;
        sW[ic][k][oc] = w[((size_t)oc * 3 + ic) * 9 + k];
    }
    __syncthreads();

    unsigned long long acc[4][8];
#pragma unroll
    for (int p = 0; p < 4; p++)
#pragma unroll
        for (int j = 0; j < 8; j++) acc[p][j] = 0ULL;

#pragma unroll
    for (int ic = 0; ic < 3; ic++) {
#pragma unroll
        for (int ky = 0; ky < 3; ky++) {
            unsigned long long vv[10];
#pragma unroll
            for (int u = 0; u < 10; u++) {
                float v = sIn[ic][r + ky][xo + u];
                vv[u] = pack2(v, v);
            }
#pragma unroll
            for (int kx = 0; kx < 3; kx++) {
                const ulonglong2* wp = (const ulonglong2*)&sW[ic][ky * 3 + kx][wid * 8];
                ulonglong2 wA = wp[0], wB = wp[1];
#pragma unroll
                for (int j = 0; j < 8; j++) {
                    ffma2(acc[0][j], wA.x, vv[kx + j]);
                    ffma2(acc[1][j], wA.y, vv[kx + j]);
                    ffma2(acc[2][j], wB.x, vv[kx + j]);
                    ffma2(acc[3][j], wB.y, vv[kx + j]);
                }
            }
        }
    }

    const int ocw = wid * 8;
    const int oy = y0p + r, ox = x0p + xo;
#pragma unroll
    for (int p = 0; p < 4; p++) {
        float blo = bias[ocw + 2*p], bhi = bias[ocw + 2*p + 1];
        float lo[8], hi[8];
#pragma unroll
        for (int j = 0; j < 8; j++) {
            float2 u = unpack2(acc[p][j]);
            lo[j] = fmaxf(u.x + blo, 0.f);
            hi[j] = fmaxf(u.y + bhi, 0.f);
        }
        float* ylo = y + (size_t)(ocw + 2*p) * HW + (size_t)oy * W + ox;
        float* yhi = ylo + HW;
        *(float4*)ylo       = make_float4(lo[0], lo[1], lo[2], lo[3]);
        *(float4*)(ylo + 4) = make_float4(lo[4], lo[5], lo[6], lo[7]);
        *(float4*)yhi       = make_float4(hi[0], hi[1], hi[2], hi[3]);
        *(float4*)(yhi + 4) = make_float4(hi[4], hi[5], hi[6], hi[7]);
    }
}

// ---------------------------------------------------------------------------
// conv2: 64->64, IC-split into two halves of 32 (z = b*2 + ihalf).
// Writes RAW partials (bias only in half 0, no ReLU) to g_buf2[ih*PHALF+..].
// TH=16 tile, CHUNK=8 (4 chunks).  grid: (180, 1, 2*B) = 720 blocks.
// ---------------------------------------------------------------------------
__global__ __launch_bounds__(256, 2)
void conv2_kernel(const float* __restrict__ w, const float* __restrict__ bias) {
    __shared__ float sIn[8][18][20];
    __shared__ float sW[8][9][64];

    int t = blockIdx.x;
    const int z = blockIdx.z;
    const int ih = z & 1, b = z >> 1;
    const bool qjob = t < 144;
    int H, ntx; long joff;
    if (qjob) { H = 192; ntx = 12; joff = 0; }
    else { t -= 144; H = 96; ntx = 6; joff = KOFF12; }
    const int W = H, HW = H * W;
    const float* x = g_buf1 + joff + (size_t)b * 64 * HW + (size_t)ih * 32 * HW;
    float* y = g_buf2 + (size_t)ih * PHALF + joff + (size_t)b * 64 * HW;

    const int tx = t % ntx, ty = t / ntx;
    const int tid = threadIdx.x;
    const int wid = tid >> 5, lane = tid & 31;
    const int r = lane >> 1, xo = (lane & 1) << 3;
    const int x0p = tx << 4, y0p = ty << 4;

    unsigned long long acc[4][8];
#pragma unroll
    for (int p = 0; p < 4; p++)
#pragma unroll
        for (int j = 0; j < 8; j++) acc[p][j] = 0ULL;

    for (int ic0 = 0; ic0 < 32; ic0 += 8) {
        __syncthreads();
        for (int i = tid; i < 8 * 324; i += 256) {
            int ic = i / 324; int rr = i % 324;
            int iy = rr / 18, ix = rr % 18;
            int gy = y0p + iy - 1, gx = x0p + ix - 1;
            float v = 0.f;
            if (gy >= 0 && gy < H && gx >= 0 && gx < W)
                v = x[(size_t)(ic0 + ic) * HW + (size_t)gy * W + gx];
            sIn[ic][iy][ix] = v;
        }
        for (int i = tid; i < 8 * 9 * 64; i += 256) {
            int oc = i & 63; int rr = i >> 6; int k = rr % 9; int ic = rr / 9;
            sW[ic][k][oc] = w[((size_t)oc * 64 + ih * 32 + ic0 + ic) * 9 + k];
        }
        __syncthreads();

#pragma unroll
        for (int ic = 0; ic < 8; ic++) {
#pragma unroll
            for (int ky = 0; ky < 3; ky++) {
                unsigned long long vv[10];
#pragma unroll
                for (int u = 0; u < 10; u++) {
                    float v = sIn[ic][r + ky][xo + u];
                    vv[u] = pack2(v, v);
                }
#pragma unroll
                for (int kx = 0; kx < 3; kx++) {
                    const ulonglong2* wp = (const ulonglong2*)&sW[ic][ky * 3 + kx][wid * 8];
                    ulonglong2 wA = wp[0], wB = wp[1];
#pragma unroll
                    for (int j = 0; j < 8; j++) {
                        ffma2(acc[0][j], wA.x, vv[kx + j]);
                        ffma2(acc[1][j], wA.y, vv[kx + j]);
                        ffma2(acc[2][j], wB.x, vv[kx + j]);
                        ffma2(acc[3][j], wB.y, vv[kx + j]);
                    }
                }
            }
        }
    }

    const int ocw = wid * 8;
    const int oy = y0p + r, ox = x0p + xo;
#pragma unroll
    for (int p = 0; p < 4; p++) {
        float blo = (ih == 0) ? bias[ocw + 2*p] : 0.f;
        float bhi = (ih == 0) ? bias[ocw + 2*p + 1] : 0.f;
        float lo[8], hi[8];
#pragma unroll
        for (int j = 0; j < 8; j++) {
            float2 u = unpack2(acc[p][j]);
            lo[j] = u.x + blo;          // RAW (no relu) — combined in conv3 loader
            hi[j] = u.y + bhi;
        }
        float* ylo = y + (size_t)(ocw + 2*p) * HW + (size_t)oy * W + ox;
        float* yhi = ylo + HW;
        *(float4*)ylo       = make_float4(lo[0], lo[1], lo[2], lo[3]);
        *(float4*)(ylo + 4) = make_float4(lo[4], lo[5], lo[6], lo[7]);
        *(float4*)yhi       = make_float4(hi[0], hi[1], hi[2], hi[3]);
        *(float4*)(yhi + 4) = make_float4(hi[4], hi[5], hi[6], hi[7]);
    }
}

// ---------------------------------------------------------------------------
// conv3: 64->128, input = relu(max2x2(A+B)) computed in loader (fused
// maxpool + partial combine).  TH=8 tile, occ 3.  grid: (90, 1, 2*B)
// z = b*2 + ocgroup.
// ---------------------------------------------------------------------------
__global__ __launch_bounds__(256, 3)
void conv3_kernel(const float* __restrict__ w, const float* __restrict__ bias) {
    __shared__ float sIn[8][10][20];
    __shared__ float sW[8][9][64];

    int t = blockIdx.x;
    const int z = blockIdx.z;
    const int b = z >> 1, ocbase = (z & 1) << 6;
    const bool qjob = t < 72;
    int H, ntx; long joff, joff4;
    if (qjob) { H = 96; ntx = 6; joff = 0; joff4 = 0; }
    else { t -= 72; H = 48; ntx = 3; joff = KOFF12; joff4 = KOFF4; }
    const int W = H, HW = H * W;
    const int W2 = 2 * W, HW2 = 4 * HW;
    const float* srcA = g_buf2 + joff + (size_t)b * 64 * HW2;
    float* y = g_buf4 + joff4 + (size_t)b * 128 * HW;

    const int tx = t % ntx, ty = t / ntx;
    const int tid = threadIdx.x;
    const int wid = tid >> 5, lane = tid & 31;
    const int r = lane >> 2, xo = (lane & 3) << 2;
    const int x0p = tx << 4, y0p = ty << 3;

    unsigned long long acc[4][4];
#pragma unroll
    for (int p = 0; p < 4; p++)
#pragma unroll
        for (int j = 0; j < 4; j++) acc[p][j] = 0ULL;

    for (int ic0 = 0; ic0 < 64; ic0 += 8) {
        __syncthreads();
        // fused loader: relu(max of 2x2 of (A+B))
        for (int i = tid; i < 8 * 180; i += 256) {
            int ic = i / 180; int rr = i % 180;
            int iy = rr / 18, ix = rr % 18;
            int gy = y0p + iy - 1, gx = x0p + ix - 1;
            float v = 0.f;
            if (gy >= 0 && gy < H && gx >= 0 && gx < W) {
                const float* a = srcA + (size_t)(ic0 + ic) * HW2 + (size_t)(2*gy) * W2 + 2*gx;
                const float* bb = a + PHALF;
                float s00 = a[0]      + bb[0];
                float s01 = a[1]      + bb[1];
                float s10 = a[W2]     + bb[W2];
                float s11 = a[W2 + 1] + bb[W2 + 1];
                v = fmaxf(fmaxf(fmaxf(s00, s01), fmaxf(s10, s11)), 0.f);
            }
            sIn[ic][iy][ix] = v;
        }
        for (int i = tid; i < 8 * 9 * 64; i += 256) {
            int oc = i & 63; int rr = i >> 6; int k = rr % 9; int ic = rr / 9;
            sW[ic][k][oc] = w[((size_t)(ocbase + oc) * 64 + ic0 + ic) * 9 + k];
        }
        __syncthreads();

#pragma unroll
        for (int ic = 0; ic < 8; ic++) {
#pragma unroll
            for (int ky = 0; ky < 3; ky++) {
                unsigned long long vv[6];
#pragma unroll
                for (int u = 0; u < 6; u++) {
                    float v = sIn[ic][r + ky][xo + u];
                    vv[u] = pack2(v, v);
                }
#pragma unroll
                for (int kx = 0; kx < 3; kx++) {
                    const ulonglong2* wp = (const ulonglong2*)&sW[ic][ky * 3 + kx][wid * 8];
                    ulonglong2 wA = wp[0], wB = wp[1];
#pragma unroll
                    for (int j = 0; j < 4; j++) {
                        ffma2(acc[0][j], wA.x, vv[kx + j]);
                        ffma2(acc[1][j], wA.y, vv[kx + j]);
                        ffma2(acc[2][j], wB.x, vv[kx + j]);
                        ffma2(acc[3][j], wB.y, vv[kx + j]);
                    }
                }
            }
        }
    }

    const int ocw = ocbase + wid * 8;
    const int oy = y0p + r, ox = x0p + xo;
#pragma unroll
    for (int p = 0; p < 4; p++) {
        float blo = bias[ocw + 2*p], bhi = bias[ocw + 2*p + 1];
        float lo[4], hi[4];
#pragma unroll
        for (int j = 0; j < 4; j++) {
            float2 u = unpack2(acc[p][j]);
            lo[j] = fmaxf(u.x + blo, 0.f);
            hi[j] = fmaxf(u.y + bhi, 0.f);
        }
        float* ylo = y + (size_t)(ocw + 2*p) * HW + (size_t)oy * W + ox;
        float* yhi = ylo + HW;
        *(float4*)ylo = make_float4(lo[0], lo[1], lo[2], lo[3]);
        *(float4*)yhi = make_float4(hi[0], hi[1], hi[2], hi[3]);
    }
}

// ---------------------------------------------------------------------------
// merged 1x1 conv 128->16 + LeakyReLU(0.2) + fused channel-ssq.
// grid: (36 + 9, B)
// ---------------------------------------------------------------------------
__global__ void conv1x1_leaky_ssq_kernel(const float* __restrict__ w,
                                         const float* __restrict__ bias) {
    __shared__ float sw[128 * 16];
    const int tid = threadIdx.x;
    for (int i = tid; i < 2048; i += 256) {
        int oc = i & 15, ic = i >> 4;
        sw[i] = w[oc * 128 + ic];
    }
    __syncthreads();
    const int bx = blockIdx.x;
    const int b = blockIdx.y;
    const float* x; float* y; float* S; int HW, pix;
    if (bx < 36) { x = g_buf4;         y = g_qf; S = g_Sq; HW = 9216; pix = bx * 256 + tid; }
    else         { x = g_buf4 + KOFF4; y = g_kf; S = g_Sk; HW = 2304; pix = (bx - 36) * 256 + tid; }

    const float* xb = x + (size_t)b * 128 * HW + pix;
    float acc[16];
#pragma unroll
    for (int o = 0; o < 16; o++) acc[o] = bias[o];
    for (int ic = 0; ic < 128; ic++) {
        const float v = xb[(size_t)ic * HW];
        const float4* wp = (const float4*)&sw[ic * 16];
#pragma unroll
        for (int o4 = 0; o4 < 4; o4++) {
            float4 w4 = wp[o4];
            acc[o4*4+0] += v * w4.x;
            acc[o4*4+1] += v * w4.y;
            acc[o4*4+2] += v * w4.z;
            acc[o4*4+3] += v * w4.w;
        }
    }
    float* yb = y + (size_t)b * 16 * HW + pix;
    float ssq = 0.f;
#pragma unroll
    for (int o = 0; o < 16; o++) {
        float v = acc[o];
        v = v > 0.f ? v : 0.2f * v;
        yb[(size_t)o * HW] = v;
        ssq += v * v;
    }
    S[(size_t)b * HW + pix] = ssq;
}

// ---------------------------------------------------------------------------
// merged patch inv-norm
// ---------------------------------------------------------------------------
__global__ void patch_invnorm_m_kernel() {
    const int nq = 2*9216;
    int i = blockIdx.x * 256 + threadIdx.x;
    const float* S; float* N; int H, W, idx;
    if (i < nq) { S = g_Sq; N = g_Nq; H = 96; W = 96; idx = i; }
    else {
        idx = i - nq;
        if (idx >= 2*2304) return;
        S = g_Sk; N = g_Nk; H = 48; W = 48;
    }
    int HW = H * W;
    int pix = idx % HW; int b = idx / HW;
    int y = pix / W, x = pix % W;
    float s = 0.f;
#pragma unroll
    for (int dy = -1; dy <= 1; dy++) {
        int ry = reflect_idx(y + dy, H);
#pragma unroll
        for (int dx = -1; dx <= 1; dx++) {
            int rx = reflect_idx(x + dx, W);
            s += S[(size_t)b * HW + (size_t)ry * W + rx];
        }
    }
    N[idx] = 1.f / fmaxf(sqrtf(s), 1e-12f);
}

// ---------------------------------------------------------------------------
// Build Qn [B][144][9216]
// ---------------------------------------------------------------------------
__global__ void build_qn_kernel() {
    const int W = 96, HW = 9216;
    int pix = blockIdx.x * 256 + threadIdx.x;
    int bf = blockIdx.y;
    int b = bf / 144, f = bf % 144;
    int c = f / 9, k = f % 9;
    int dy = k / 3 - 1, dx = k % 3 - 1;
    int y = pix / W, x = pix % W;
    int ry = reflect_idx(y + dy, 96), rx = reflect_idx(x + dx, 96);
    g_Qn[((size_t)b * 144 + f) * HW + pix] =
        g_qf[((size_t)b * 16 + c) * HW + (size_t)ry * W + rx] * g_Nq[(size_t)b * HW + pix];
}

// ---------------------------------------------------------------------------
// Build Wn [B][2304][144]
// ---------------------------------------------------------------------------
__global__ void build_wn_kernel() {
    const int W = 48, HW = 2304;
    int idx = blockIdx.x * 256 + threadIdx.x;
    if (idx >= B_ * HW * 144) return;
    int f = idx % 144; int r = idx / 144;
    int kp = r % HW; int b = r / HW;
    int c = f / 9, k = f % 9;
    int dy = k / 3 - 1, dx = k % 3 - 1;
    int y = kp / W, x = kp % W;
    int ry = reflect_idx(y + dy, 48), rx = reflect_idx(x + dx, 48);
    g_Wn[((size_t)b * HW + kp) * 144 + f] =
        g_kf[((size_t)b * 16 + c) * HW + (size_t)ry * W + rx] * g_Nk[(size_t)b * HW + kp];
}

// ---------------------------------------------------------------------------
// Fused cosine-GEMM + max/argmax (R4-proven config): f32x2, split-K=2, occ 2.
// grid: (72, B, 2)
// ---------------------------------------------------------------------------
__global__ __launch_bounds__(256, 2)
void match_f32x2_kernel() {
    const int LQ = 9216, LK = 2304, F = 144;
    __shared__ float sA[48][64];
    __shared__ float sB[48][128];
    __shared__ float rV[8][128];
    __shared__ int   rI[8][128];

    const int tid = threadIdx.x;
    const int wid = tid >> 5, lane = tid & 31;
    const int q0 = blockIdx.x << 7;
    const int b = blockIdx.y;
    const int z = blockIdx.z;
    const float* Wb = g_Wn + (size_t)b * LK * F;
    const float* Qb = g_Qn + (size_t)b * F * LQ;

    const int lk = tid & 63;
    const int cb = (tid >> 6) * 3;
    const int fB = tid >> 5;
    const int cB = tid & 31;

    float bestV[4] = {-1e30f, -1e30f, -1e30f, -1e30f};
    int   bestI[4] = {0, 0, 0, 0};

    const int kbeg = z * 1152, kend = kbeg + 1152;
    for (int k0 = kbeg; k0 < kend; k0 += 64) {
        unsigned long long acc[4][4];
#pragma unroll
        for (int p = 0; p < 4; p++)
#pragma unroll
            for (int j = 0; j < 4; j++) acc[p][j] = 0ULL;

        for (int f0 = 0; f0 < F; f0 += 48) {
            __syncthreads();
#pragma unroll
            for (int e = 0; e < 3; e++) {
                int c = cb + e;
                float4 a4 = *(const float4*)&Wb[(size_t)(k0 + lk) * F + f0 + c * 4];
                sA[c*4+0][lk] = a4.x; sA[c*4+1][lk] = a4.y;
                sA[c*4+2][lk] = a4.z; sA[c*4+3][lk] = a4.w;
            }
#pragma unroll
            for (int p = 0; p < 6; p++) {
                int f = fB + (p << 3);
                *(float4*)&sB[f][cB * 4] =
                    *(const float4*)&Qb[(size_t)(f0 + f) * LQ + q0 + cB * 4];
            }
            __syncthreads();

#pragma unroll 6
            for (int f = 0; f < 48; f++) {
                ulonglong2 a01 = *(const ulonglong2*)&sA[f][wid * 8];
                ulonglong2 a23 = *(const ulonglong2*)&sA[f][wid * 8 + 4];
                float4 b4 = *(const float4*)&sB[f][lane * 4];
                unsigned long long b0 = pack2(b4.x, b4.x);
                unsigned long long b1 = pack2(b4.y, b4.y);
                unsigned long long b2 = pack2(b4.z, b4.z);
                unsigned long long b3 = pack2(b4.w, b4.w);
                ffma2(acc[0][0], a01.x, b0); ffma2(acc[0][1], a01.x, b1);
                ffma2(acc[0][2], a01.x, b2); ffma2(acc[0][3], a01.x, b3);
                ffma2(acc[1][0], a01.y, b0); ffma2(acc[1][1], a01.y, b1);
                ffma2(acc[1][2], a01.y, b2); ffma2(acc[1][3], a01.y, b3);
                ffma2(acc[2][0], a23.x, b0); ffma2(acc[2][1], a23.x, b1);
                ffma2(acc[2][2], a23.x, b2); ffma2(acc[2][3], a23.x, b3);
                ffma2(acc[3][0], a23.y, b0); ffma2(acc[3][1], a23.y, b1);
                ffma2(acc[3][2], a23.y, b2); ffma2(acc[3][3], a23.y, b3);
            }
        }

        const int kbase = k0 + wid * 8;
#pragma unroll
        for (int p = 0; p < 4; p++) {
#pragma unroll
            for (int j = 0; j < 4; j++) {
                float2 u = unpack2(acc[p][j]);
                if (u.x > bestV[j]) { bestV[j] = u.x; bestI[j] = kbase + 2*p; }
                if (u.y > bestV[j]) { bestV[j] = u.y; bestI[j] = kbase + 2*p + 1; }
            }
        }
    }

#pragma unroll
    for (int j = 0; j < 4; j++) {
        rV[wid][lane * 4 + j] = bestV[j];
        rI[wid][lane * 4 + j] = bestI[j];
    }
    __syncthreads();
    if (tid < 128) {
        float bv = rV[0][tid]; int bi = rI[0][tid];
#pragma unroll
        for (int t = 1; t < 8; t++) {
            float v = rV[t][tid];
            if (v > bv) { bv = v; bi = rI[t][tid]; }
        }
        int o = (b * 2 + z) * LQ + q0 + tid;
        g_pV[o] = bv;
        g_pI[o] = bi;
    }
}

// ---------------------------------------------------------------------------
// merge the two split-K halves (half0 wins ties = lower key index)
// ---------------------------------------------------------------------------
__global__ void match_reduce_kernel(float* __restrict__ relout,
                                    float* __restrict__ idxout) {
    int i = blockIdx.x * 256 + threadIdx.x;
    if (i >= 2 * 9216) return;
    int b = i / 9216, q = i % 9216;
    float v0 = g_pV[(b*2+0)*9216 + q]; int i0 = g_pI[(b*2+0)*9216 + q];
    float v1 = g_pV[(b*2+1)*9216 + q]; int i1 = g_pI[(b*2+1)*9216 + q];
    float bv = v0; int bi = i0;
    if (v1 > bv) { bv = v1; bi = i1; }
    relout[i] = bv;
    idxout[i] = (float)bi;
}

// ---------------------------------------------------------------------------
// launcher — ONLY kernel launches
// ---------------------------------------------------------------------------
extern "C" void kernel_launch(void* const* d_in, const int* in_sizes, int n_in,
                              void* d_out, int out_size) {
    const float* query = (const float*)d_in[0];
    const float* key   = (const float*)d_in[1];
    const float* w1 = (const float*)d_in[2];
    const float* b1 = (const float*)d_in[3];
    const float* w2 = (const float*)d_in[4];
    const float* b2 = (const float*)d_in[5];
    const float* w3 = (const float*)d_in[6];
    const float* b3 = (const float*)d_in[7];
    const float* wm = (const float*)d_in[8];
    const float* bm = (const float*)d_in[9];
    float* out = (float*)d_out;

    // conv1 (avgpool fused into k-job loader)
    conv1_kernel<<<dim3(180, 1, 2), 256>>>(query, key, w1, b1);

    // conv2 IC-split: 720 blocks (z = b*2 + ichalf), raw partials
    conv2_kernel<<<dim3(180, 1, 4), 256>>>(w2, b2);

    // conv3 (maxpool + partial-combine fused into loader), occ 3
    conv3_kernel<<<dim3(90, 1, 4), 256>>>(w3, b3);

    // merged 1x1 + leaky + ssq
    conv1x1_leaky_ssq_kernel<<<dim3(45, 2), 256>>>(wm, bm);

    // merged patch inv-norms
    patch_invnorm_m_kernel<<<(2*(9216 + 2304) + 255)/256, 256>>>();

    // normalized unfold tensors
    build_qn_kernel<<<dim3(36, 2*144), 256>>>();
    build_wn_kernel<<<(2*2304*144 + 255)/256, 256>>>();

    // fused cosine-sim GEMM + max/argmax, split-K=2 then merge
    match_f32x2_kernel<<<dim3(72, 2, 2), 256>>>();
    match_reduce_kernel<<<(2*9216 + 255)/256, 256>>>(out, out + 2*9216);
}